// round 1
// baseline (speedup 1.0000x reference)
#include <cuda_runtime.h>
#include <cstdint>
#include <math.h>

#define NTOK 8192
#define DDIM 1024
#define FDIM 4096
#define NEXP 8

#define BM 128
#define BN 128
#define BK 32
#define ASTR 36      // A smem row stride (floats): bank-stride 4, 144B (16B aligned)
#define BSTR 136     // B smem row stride (floats): bank-stride 8, 544B (16B aligned)
#define MAXTILES 71  // worst case sum ceil(cnt_e/128) = 64 + 7
#define SMEM_BYTES (2*(BM*ASTR + BK*BSTR)*4)

// ---------------- device scratch (static, allocation-free) ----------------
__device__ float g_H[(size_t)(NTOK + BM) * FDIM];   // permuted hidden activations (padded rows)
__device__ int   g_eid[NTOK];
__device__ float g_gate[NTOK];
__device__ int   g_counts[NEXP];
__device__ int   g_cursor[NEXP];
__device__ int   g_offsets[NEXP + 1];
__device__ int   g_tile_e[MAXTILES];
__device__ int   g_tile_row[MAXTILES];
__device__ int   g_ntiles;
__device__ int   g_perm[NTOK];

// ---------------- helpers ----------------
__device__ __forceinline__ uint32_t tf32u(float x) {
    uint32_t u;
    asm("cvt.rna.tf32.f32 %0, %1;" : "=r"(u) : "f"(x));
    return u;
}

__device__ __forceinline__ void mma8(float* c, const uint32_t* a, uint32_t b0, uint32_t b1) {
    asm volatile(
        "mma.sync.aligned.m16n8k8.row.col.f32.tf32.tf32.f32 "
        "{%0,%1,%2,%3}, {%4,%5,%6,%7}, {%8,%9}, {%0,%1,%2,%3};\n"
        : "+f"(c[0]), "+f"(c[1]), "+f"(c[2]), "+f"(c[3])
        : "r"(a[0]), "r"(a[1]), "r"(a[2]), "r"(a[3]), "r"(b0), "r"(b1));
}

__device__ __forceinline__ void cp16(float* dst, const float* src, bool pred) {
    uint32_t d = (uint32_t)__cvta_generic_to_shared(dst);
    int sz = pred ? 16 : 0;
    asm volatile("cp.async.cg.shared.global [%0], [%1], 16, %2;\n" :: "r"(d), "l"(src), "r"(sz));
}
__device__ __forceinline__ void cp_commit() { asm volatile("cp.async.commit_group;\n"); }
template<int N> __device__ __forceinline__ void cp_wait() {
    asm volatile("cp.async.wait_group %0;\n" :: "n"(N));
}

// ---------------- tiny kernels ----------------
__global__ void zero_kernel() {
    int t = threadIdx.x;
    if (t < NEXP) { g_counts[t] = 0; g_cursor[t] = 0; }
}

__global__ void router_kernel(const float* __restrict__ x,
                              const float* __restrict__ Wr,
                              const float* __restrict__ br) {
    __shared__ float sWrT[NEXP * DDIM];  // transposed: [e][d]
    int tid = threadIdx.x;
    for (int i = tid; i < NEXP * DDIM; i += 256) {
        int d = i >> 3, e = i & 7;
        sWrT[e * DDIM + d] = Wr[i];
    }
    __syncthreads();

    int warp = tid >> 5, lane = tid & 31;
    int tok = blockIdx.x * 8 + warp;
    const float4* xr = (const float4*)(x + (size_t)tok * DDIM);

    float acc[NEXP];
#pragma unroll
    for (int e = 0; e < NEXP; e++) acc[e] = 0.f;

#pragma unroll
    for (int it = 0; it < 8; it++) {
        int d4 = lane + it * 32;
        float4 xv = xr[d4];
#pragma unroll
        for (int e = 0; e < NEXP; e++) {
            float4 wv = ((const float4*)(sWrT + e * DDIM))[d4];
            acc[e] += xv.x * wv.x + xv.y * wv.y + xv.z * wv.z + xv.w * wv.w;
        }
    }
#pragma unroll
    for (int e = 0; e < NEXP; e++)
#pragma unroll
        for (int o = 16; o; o >>= 1) acc[e] += __shfl_xor_sync(0xffffffffu, acc[e], o);

    if (lane == 0) {
        float l[NEXP];
#pragma unroll
        for (int e = 0; e < NEXP; e++) l[e] = acc[e] + br[e];
        int best = 0;
#pragma unroll
        for (int e = 1; e < NEXP; e++) if (l[e] > l[best]) best = e;  // first-max like jnp.argmax
        float mx = l[best];
        float se = 0.f;
#pragma unroll
        for (int e = 0; e < NEXP; e++) se += expf(l[e] - mx);
        g_eid[tok] = best;
        g_gate[tok] = 1.0f / se;  // exp(0)/se
        atomicAdd(&g_counts[best], 1);
    }
}

__global__ void plan_kernel() {
    int off = 0, nt = 0;
    g_offsets[0] = 0;
    for (int e = 0; e < NEXP; e++) {
        int c = g_counts[e];
        int start = off;
        off += c;
        g_offsets[e + 1] = off;
        int tiles = (c + BM - 1) >> 7;
        for (int i = 0; i < tiles; i++) { g_tile_e[nt] = e; g_tile_row[nt] = start + i * BM; nt++; }
    }
    g_ntiles = nt;
}

__global__ void scatter_kernel() {
    int t = blockIdx.x * 256 + threadIdx.x;
    if (t < NTOK) {
        int e = g_eid[t];
        int p = atomicAdd(&g_cursor[e], 1);
        g_perm[g_offsets[e] + p] = t;
    }
}

// ---------------- grouped tf32 GEMM ----------------
// G1: A = gather(x, perm) [K=DDIM], B = W1[e], epilogue gelu -> g_H (permuted rows)
// G2: A = g_H (contiguous) [K=FDIM], B = W2[e], epilogue gate*scatter -> out
template<int KTOT, int NTOT, bool G1>
__global__ void __launch_bounds__(256)
moe_gemm_kernel(const float* __restrict__ Aglob, const float* __restrict__ Wglob,
                const float* __restrict__ bias, float* __restrict__ Outglob) {
    int ty = blockIdx.y;
    if (ty >= g_ntiles) return;
    int e = g_tile_e[ty];
    int row0 = g_tile_row[ty];
    int rows = g_offsets[e + 1] - row0;
    if (rows > BM) rows = BM;
    int n0 = blockIdx.x * BN;

    const float* Abase = G1 ? Aglob : g_H;
    float*       Ob    = G1 ? g_H   : Outglob;
    const float* Bw = Wglob + (size_t)e * KTOT * NTOT;

    extern __shared__ float sm[];
    float* Abuf[2]; float* Bbuf[2];
    Abuf[0] = sm;
    Bbuf[0] = Abuf[0] + BM * ASTR;
    Abuf[1] = Bbuf[0] + BK * BSTR;
    Bbuf[1] = Abuf[1] + BM * ASTR;
    __shared__ float sbias[BN];

    int tid = threadIdx.x;
    // A loader: 4 rows/thread, 16B per row-chunk
    int ar = tid >> 3;
    int akv = tid & 7;
    const float* aptr[4];
    bool avalid[4];
#pragma unroll
    for (int i = 0; i < 4; i++) {
        int r = ar + i * 32;
        bool v = r < rows;
        int src_row;
        if (G1) { src_row = v ? g_perm[row0 + r] : 0; avalid[i] = v; }
        else    { src_row = row0 + r; avalid[i] = true; }  // H padded, garbage rows never written out
        aptr[i] = Abase + (size_t)src_row * KTOT + akv * 4;
    }
    // B loader
    int bkr = tid >> 5;
    int bnv = tid & 31;

    if (tid < BN) sbias[tid] = bias[(size_t)e * NTOT + n0 + tid];

    float c[2][8][4];
#pragma unroll
    for (int mf = 0; mf < 2; mf++)
#pragma unroll
        for (int nf = 0; nf < 8; nf++)
#pragma unroll
            for (int i = 0; i < 4; i++) c[mf][nf][i] = 0.f;

    int wid = tid >> 5, lane = tid & 31;
    int wm = wid & 3, wn = wid >> 2;
    int mbase = wm * 32, nbase = wn * 64;
    int g = lane >> 2, t4 = lane & 3;

    constexpr int KT = KTOT / BK;

    // prologue: tile 0
    {
        int k0 = 0;
#pragma unroll
        for (int i = 0; i < 4; i++)
            cp16(&Abuf[0][(ar + i * 32) * ASTR + akv * 4], aptr[i] + k0, avalid[i]);
#pragma unroll
        for (int i = 0; i < 4; i++) {
            int kr = bkr + i * 8;
            cp16(&Bbuf[0][kr * BSTR + bnv * 4], Bw + (size_t)(k0 + kr) * NTOT + n0 + bnv * 4, true);
        }
        cp_commit();
    }

    for (int t = 0; t < KT; t++) {
        if (t + 1 < KT) {
            int s = (t + 1) & 1;
            int k0 = (t + 1) * BK;
#pragma unroll
            for (int i = 0; i < 4; i++)
                cp16(&Abuf[s][(ar + i * 32) * ASTR + akv * 4], aptr[i] + k0, avalid[i]);
#pragma unroll
            for (int i = 0; i < 4; i++) {
                int kr = bkr + i * 8;
                cp16(&Bbuf[s][kr * BSTR + bnv * 4], Bw + (size_t)(k0 + kr) * NTOT + n0 + bnv * 4, true);
            }
            cp_commit();
            cp_wait<1>();
        } else {
            cp_wait<0>();
        }
        __syncthreads();

        const float* Ab = Abuf[t & 1];
        const float* Bb = Bbuf[t & 1];
#pragma unroll
        for (int ks = 0; ks < 4; ks++) {
            int k = ks * 8;
            uint32_t afr[2][4];
#pragma unroll
            for (int mf = 0; mf < 2; mf++) {
                int r = mbase + mf * 16 + g;
                afr[mf][0] = tf32u(Ab[(r)     * ASTR + k + t4]);
                afr[mf][1] = tf32u(Ab[(r + 8) * ASTR + k + t4]);
                afr[mf][2] = tf32u(Ab[(r)     * ASTR + k + t4 + 4]);
                afr[mf][3] = tf32u(Ab[(r + 8) * ASTR + k + t4 + 4]);
            }
#pragma unroll
            for (int nf = 0; nf < 8; nf++) {
                int col = nbase + nf * 8 + g;
                uint32_t b0 = tf32u(Bb[(k + t4)     * BSTR + col]);
                uint32_t b1 = tf32u(Bb[(k + 4 + t4) * BSTR + col]);
                mma8(c[0][nf], afr[0], b0, b1);
                mma8(c[1][nf], afr[1], b0, b1);
            }
        }
        __syncthreads();
    }

    // epilogue
#pragma unroll
    for (int mf = 0; mf < 2; mf++) {
#pragma unroll
        for (int half = 0; half < 2; half++) {
            int ml = mbase + mf * 16 + g + half * 8;
            bool valid = ml < rows;
            if (!valid) continue;
            size_t grow;
            float gate = 1.f;
            if (G1) {
                grow = (size_t)(row0 + ml);
            } else {
                int tok = g_perm[row0 + ml];
                gate = g_gate[tok];
                grow = (size_t)tok;
            }
            float* orow = Ob + grow * NTOT + n0;
#pragma unroll
            for (int nf = 0; nf < 8; nf++) {
#pragma unroll
                for (int q = 0; q < 2; q++) {
                    int nl = nbase + nf * 8 + t4 * 2 + q;
                    float v = c[mf][nf][half * 2 + q] + sbias[nl];
                    if (G1) {
                        v = 0.5f * v * (1.0f + erff(v * 0.70710678118654752f));  // exact gelu
                        orow[nl] = v;
                    } else {
                        orow[nl] = v * gate;
                    }
                }
            }
        }
    }
}

// ---------------- launch ----------------
extern "C" void kernel_launch(void* const* d_in, const int* in_sizes, int n_in,
                              void* d_out, int out_size) {
    const float* x  = (const float*)d_in[0];
    const float* W1 = (const float*)d_in[1];
    const float* b1 = (const float*)d_in[2];
    const float* W2 = (const float*)d_in[3];
    const float* b2 = (const float*)d_in[4];
    const float* Wr = (const float*)d_in[5];
    const float* br = (const float*)d_in[6];
    float* out = (float*)d_out;

    cudaFuncSetAttribute(moe_gemm_kernel<DDIM, FDIM, true>,
                         cudaFuncAttributeMaxDynamicSharedMemorySize, SMEM_BYTES);
    cudaFuncSetAttribute(moe_gemm_kernel<FDIM, DDIM, false>,
                         cudaFuncAttributeMaxDynamicSharedMemorySize, SMEM_BYTES);

    zero_kernel<<<1, 32>>>();
    router_kernel<<<NTOK / 8, 256>>>(x, Wr, br);
    plan_kernel<<<1, 1>>>();
    scatter_kernel<<<NTOK / 256, 256>>>();

    dim3 g1(FDIM / BN, MAXTILES);
    moe_gemm_kernel<DDIM, FDIM, true><<<g1, 256, SMEM_BYTES>>>(x, W1, b1, nullptr);

    dim3 g2(DDIM / BN, MAXTILES);
    moe_gemm_kernel<FDIM, DDIM, false><<<g2, 256, SMEM_BYTES>>>(nullptr, W2, b2, out);
}